// round 10
// baseline (speedup 1.0000x reference)
#include <cuda_runtime.h>
#include <cuda_fp16.h>
#include <cstdint>

// ---------------------------------------------------------------------------
// TriangularAttention: B=2, S=48 -> N=2304, D=256, H=8, DH=32
// Round 10: GEMMs retiled to 64x64 CTAs (grids 864/288, halved dep chains,
//           2 cp.async per thread per chunk). Attention unchanged from R9.
// ---------------------------------------------------------------------------

constexpr int B_  = 2;
constexpr int S_  = 48;
constexpr int D_  = 256;
constexpr int H_  = 8;
constexpr int DH_ = 32;
constexpr int N_  = S_ * S_;     // 2304
constexpr int M_  = B_ * N_;     // 4608
constexpr int BH_ = B_ * H_;     // 16

// fp16 storage (uint4 for 16B alignment)
__device__ uint4 g_qh_[BH_ * N_ * DH_ / 8];
__device__ uint4 g_kh_[BH_ * N_ * DH_ / 8];
__device__ uint4 g_vh_[BH_ * N_ * DH_ / 8];
__device__ uint4 g_xh_[M_ * D_ / 8];
__device__ uint4 g_wh_[4 * D_ * D_ / 8];
__device__ uint4 g_ctxh_[M_ * D_ / 8];

// softmax: p = 2^(q·k·CS2 − C2); C2 cancels in the divide.
constexpr float CS2F = 0.17677669529663687f * 1.4426950408889634f;
constexpr float C2F  = 8.0f * 1.4426950408889634f;

// ---------------- helpers ---------------------------------------------------
__device__ __forceinline__ uint32_t f16x2(float hi, float lo) {  // {hi,lo}
    uint32_t r;
    asm("cvt.rn.f16x2.f32 %0, %1, %2;" : "=r"(r) : "f"(hi), "f"(lo));
    return r;
}
__device__ __forceinline__ uint32_t hadd2(uint32_t a, uint32_t b) {
    uint32_t d;
    asm("add.rn.f16x2 %0, %1, %2;" : "=r"(d) : "r"(a), "r"(b));
    return d;
}
__device__ __forceinline__ uint32_t h2ex2(uint32_t a) {
    uint32_t d;
    asm("ex2.approx.f16x2 %0, %1;" : "=r"(d) : "r"(a));
    return d;
}
__device__ __forceinline__ float2 h2f2(uint32_t h) {
    float lo, hi;
    asm("{ .reg .b16 l, m; mov.b32 {l, m}, %2;\n\t"
        "cvt.f32.f16 %0, l; cvt.f32.f16 %1, m; }"
        : "=f"(lo), "=f"(hi) : "r"(h));
    return make_float2(lo, hi);
}
__device__ __forceinline__ uint32_t smem_u32(const void* p) {
    uint32_t a;
    asm("{ .reg .u64 t; cvta.to.shared.u64 t, %1; cvt.u32.u64 %0, t; }"
        : "=r"(a) : "l"(p));
    return a;
}
__device__ __forceinline__ void mma_f16(float* d, const uint32_t* a,
                                        uint32_t b0, uint32_t b1) {
    asm volatile(
        "mma.sync.aligned.m16n8k16.row.col.f32.f16.f16.f32 "
        "{%0,%1,%2,%3}, {%4,%5,%6,%7}, {%8,%9}, {%0,%1,%2,%3};"
        : "+f"(d[0]), "+f"(d[1]), "+f"(d[2]), "+f"(d[3])
        : "r"(a[0]), "r"(a[1]), "r"(a[2]), "r"(a[3]), "r"(b0), "r"(b1));
}
__device__ __forceinline__ void ldsm4(uint32_t* r, uint32_t addr) {   // non-trans
    asm volatile(
        "ldmatrix.sync.aligned.m8n8.x4.shared.b16 {%0,%1,%2,%3}, [%4];"
        : "=r"(r[0]), "=r"(r[1]), "=r"(r[2]), "=r"(r[3]) : "r"(addr));
}
__device__ __forceinline__ void ldsm4t(uint32_t* r, uint32_t addr) {  // trans
    asm volatile(
        "ldmatrix.sync.aligned.m8n8.x4.trans.shared.b16 {%0,%1,%2,%3}, [%4];"
        : "=r"(r[0]), "=r"(r[1]), "=r"(r[2]), "=r"(r[3]) : "r"(addr));
}
__device__ __forceinline__ void cpa16(uint32_t dst, const void* src) {
    asm volatile("cp.async.cg.shared.global [%0], [%1], 16;"
                 :: "r"(dst), "l"(src));
}
__device__ __forceinline__ void cp_commit() {
    asm volatile("cp.async.commit_group;");
}
template <int NWAIT>
__device__ __forceinline__ void cp_wait() {
    asm volatile("cp.async.wait_group %0;" :: "n"(NWAIT));
}

// ---------------------------------------------------------------------------
// One-shot fp32 -> fp16 conversion: x and all four weight matrices.
// ---------------------------------------------------------------------------
__global__ __launch_bounds__(256) void cvt_kernel(
    const float* __restrict__ x,
    const float* __restrict__ Wq, const float* __restrict__ Wk,
    const float* __restrict__ Wv, const float* __restrict__ Wo,
    __half* __restrict__ xh, __half* __restrict__ wh)
{
    const int tid    = blockIdx.x * 256 + threadIdx.x;
    const int stride = gridDim.x * 256;
    auto seg = [&](const float* s, __half* d, int n4) {
        for (int i = tid; i < n4; i += stride) {
            float4 v = ((const float4*)s)[i];
            uint2 h;
            h.x = f16x2(v.y, v.x);
            h.y = f16x2(v.w, v.z);
            ((uint2*)d)[i] = h;
        }
    };
    seg(x,  xh,                M_ * D_ / 4);
    seg(Wq, wh,                D_ * D_ / 4);
    seg(Wk, wh + D_ * D_,      D_ * D_ / 4);
    seg(Wv, wh + 2 * D_ * D_,  D_ * D_ / 4);
    seg(Wo, wh + 3 * D_ * D_,  D_ * D_ / 4);
}

// ---------------------------------------------------------------------------
// fp16 GEMM, 64x64 CTA tile: out[M,256] = A[M,256] @ W[256,256] + bias.
// 8 warps (2 row x 4 col), k-chunks of 32, cp.async double buffering.
// A [row][k] 80B stride (ldsm -> A-frag); W [k][c] 144B stride (ldsm.trans).
// QKV=1: three fp16 head-major outputs (z selects), q scaled by CS2.
// QKV=0: single f32 row-major output.
// ---------------------------------------------------------------------------
constexpr int GA_BYTES = 64 * 80;     // 5120
constexpr int GW_BYTES = 32 * 144;    // 4608
constexpr int GSM_BYTES = 2 * GA_BYTES + 2 * GW_BYTES;   // 19456

template <int QKV>
__global__ __launch_bounds__(256) void gemm_mma_kernel(
    const __half* __restrict__ Ah, const __half* __restrict__ Whb,
    const float* __restrict__ bias0, const float* __restrict__ bias1,
    const float* __restrict__ bias2,
    __half* __restrict__ o0h, __half* __restrict__ o1h,
    __half* __restrict__ o2h, float* __restrict__ outf)
{
    extern __shared__ __align__(16) char smc[];

    const int z = blockIdx.z;
    const __half* W   = Whb + (size_t)z * D_ * D_;
    const float* bias = (z == 0) ? bias0 : (z == 1) ? bias1 : bias2;
    __half* oh        = (z == 0) ? o0h : (z == 1) ? o1h : o2h;
    const float sc    = (QKV && z == 0) ? CS2F : 1.0f;

    const int tid  = threadIdx.x;
    const int warp = tid >> 5;
    const int lane = tid & 31;
    const int gid  = lane >> 2;
    const int tig  = lane & 3;
    const int wr   = warp & 1;          // 2 row groups of 32
    const int wc   = warp >> 1;         // 4 col groups of 16
    const int c0   = blockIdx.x * 64;
    const int m0   = blockIdx.y * 64;
    const int mm   = lane >> 3;
    const int mr   = lane & 7;

    const uint32_t sb = smem_u32(smc);

    float acc[2][2][4];
#pragma unroll
    for (int m = 0; m < 2; m++)
#pragma unroll
        for (int n = 0; n < 2; n++)
#pragma unroll
            for (int r = 0; r < 4; r++) acc[m][n][r] = 0.f;

    auto load_chunk = [&](int k0, int buf) {
        uint32_t as = sb + buf * GA_BYTES;
        uint32_t ws = sb + 2 * GA_BYTES + buf * GW_BYTES;
        const char* Ab = (const char*)Ah + ((size_t)m0 * 256 + k0) * 2;
        const char* Wb = (const char*)W + ((size_t)k0 * 256 + c0) * 2;
        {
            int row = tid >> 2, c = tid & 3;       // 64 rows x 4 x 16B
            cpa16(as + row * 80 + c * 16, Ab + (size_t)row * 512 + c * 16);
        }
        {
            int kk = tid >> 3, c8 = tid & 7;       // 32 k x 8 x 16B
            cpa16(ws + kk * 144 + c8 * 16, Wb + (size_t)kk * 512 + c8 * 16);
        }
    };

    load_chunk(0, 0);
    cp_commit();

#pragma unroll 1
    for (int kc = 0; kc < 8; kc++) {
        const int buf = kc & 1;
        cp_wait<0>();
        __syncthreads();
        if (kc + 1 < 8) {
            load_chunk((kc + 1) * 32, buf ^ 1);
            cp_commit();
        }

        const uint32_t as = sb + buf * GA_BYTES;
        const uint32_t ws = sb + 2 * GA_BYTES + buf * GW_BYTES;

#pragma unroll
        for (int h = 0; h < 2; h++) {
            uint32_t a[2][4];
#pragma unroll
            for (int mt = 0; mt < 2; mt++) {
                uint32_t addr = as
                    + (uint32_t)(wr * 32 + mt * 16 + (mm & 1) * 8 + mr) * 80
                    + (uint32_t)(h * 32 + (mm >> 1) * 16);
                ldsm4(a[mt], addr);
            }
            uint32_t w[4];
            {
                uint32_t addr = ws
                    + (uint32_t)(h * 16 + (mm & 1) * 8 + mr) * 144
                    + (uint32_t)(wc * 16 + (mm >> 1) * 8) * 2;
                ldsm4t(w, addr);
            }
            mma_f16(acc[0][0], a[0], w[0], w[1]);
            mma_f16(acc[0][1], a[0], w[2], w[3]);
            mma_f16(acc[1][0], a[1], w[0], w[1]);
            mma_f16(acc[1][1], a[1], w[2], w[3]);
        }
        __syncthreads();
    }

#pragma unroll
    for (int n = 0; n < 2; n++) {
        int c = c0 + wc * 16 + n * 8 + 2 * tig;
        float bv0 = bias[c], bv1 = bias[c + 1];
#pragma unroll
        for (int m = 0; m < 2; m++) {
            int row = m0 + wr * 32 + m * 16 + gid;
            if (QKV) {
                int hh = c >> 5;
                int dh = c & 31;
                int b  = row / N_;
                int nn = row - b * N_;
                __half* p = oh + (((size_t)(b * H_ + hh)) * N_ + nn) * DH_ + dh;
                *(uint32_t*)p = f16x2((acc[m][n][1] + bv1) * sc,
                                      (acc[m][n][0] + bv0) * sc);
                *(uint32_t*)(p + 8 * DH_) = f16x2((acc[m][n][3] + bv1) * sc,
                                                  (acc[m][n][2] + bv0) * sc);
            } else {
                float* p = outf + (size_t)row * 256 + c;
                *(float2*)p = make_float2(acc[m][n][0] + bv0, acc[m][n][1] + bv1);
                *(float2*)(p + 8 * 256) =
                    make_float2(acc[m][n][2] + bv0, acc[m][n][3] + bv1);
            }
        }
    }
}

// ---------------------------------------------------------------------------
// fp16 flash attention (unchanged from round 9).
// ---------------------------------------------------------------------------
constexpr int NTILE = N_ / 128;   // 18
constexpr int KB0 = 0;
constexpr int KB1 = 128 * 80;     // 10240
constexpr int VB0 = 2 * 128 * 80;
constexpr int VB1 = VB0 + 128 * 80;
constexpr int SMEM_ATTN_BYTES = VB1 + 128 * 80;  // 40960

__global__ __launch_bounds__(256, 2) void attn_mma_kernel(
    const __half* __restrict__ Qh, const __half* __restrict__ Kh,
    const __half* __restrict__ Vh, __half* __restrict__ Ch)
{
    extern __shared__ __align__(16) float smf[];
    const int tid  = threadIdx.x;
    const int warp = tid >> 5;
    const int lane = tid & 31;
    const int gid  = lane >> 2;
    const int tig  = lane & 3;
    const int wq   = warp & 3;
    const int wk   = warp >> 2;
    const int bh   = blockIdx.y;
    const int qt   = blockIdx.x;
    const int mm   = lane >> 3;
    const int mr   = lane & 7;

    const uint32_t sb = smem_u32(smf);

    const __half* Qg = Qh + ((size_t)bh * N_ + qt * 128) * DH_;
    const __half* Kg = Kh + (size_t)bh * N_ * DH_;
    const __half* Vg = Vh + (size_t)bh * N_ * DH_;

    // ---- Q fp16 A-frags (pre-scaled at projection): direct uint loads ----
    uint32_t qa[2][2][4];
#pragma unroll
    for (int m = 0; m < 2; m++) {
        const __half* r0 = Qg + (size_t)(wq * 32 + m * 16 + gid) * DH_;
        const __half* r1 = r0 + 8 * DH_;
#pragma unroll
        for (int h = 0; h < 2; h++) {
            int k0 = h * 16 + 2 * tig;
            qa[m][h][0] = *(const uint32_t*)(r0 + k0);
            qa[m][h][1] = *(const uint32_t*)(r1 + k0);
            qa[m][h][2] = *(const uint32_t*)(r0 + k0 + 8);
            qa[m][h][3] = *(const uint32_t*)(r1 + k0 + 8);
        }
    }

    float oacc[2][4][4];
#pragma unroll
    for (int m = 0; m < 2; m++)
#pragma unroll
        for (int n = 0; n < 4; n++)
#pragma unroll
            for (int r = 0; r < 4; r++) oacc[m][n][r] = 0.f;
    float lp[2][2] = {{0.f, 0.f}, {0.f, 0.f}};

    // ---- cp.async tile loader: K,V 128 x 64B rows -> 80B stride SMEM ----
    auto load_tile = [&](int t, int buf) {
        uint32_t kd = sb + (buf ? KB1 : KB0);
        uint32_t vd = sb + (buf ? VB1 : VB0);
        const char* ks = (const char*)(Kg + (size_t)t * 128 * DH_);
        const char* vs = (const char*)(Vg + (size_t)t * 128 * DH_);
#pragma unroll
        for (int r = 0; r < 2; r++) {
            int idx = tid + r * 256;           // 0..511
            int row = idx >> 2, c = idx & 3;
            cpa16(kd + row * 80 + c * 16, ks + (size_t)row * 64 + c * 16);
            cpa16(vd + row * 80 + c * 16, vs + (size_t)row * 64 + c * 16);
        }
    };

    load_tile(0, 0);
    cp_commit();

    for (int t = 0; t < NTILE; t++) {
        const int buf = t & 1;
        cp_wait<0>();
        __syncthreads();
        if (t + 1 < NTILE) {
            load_tile(t + 1, buf ^ 1);
            cp_commit();
        }

        const uint32_t kbb = sb + (buf ? KB1 : KB0);
        const uint32_t vbb = sb + (buf ? VB1 : VB0);

#pragma unroll
        for (int g = 0; g < 4; g++) {
            const int kb = wk * 64 + g * 16;

            // ---- S = (scaled Q)·K^T − C2, fp16 MMA ----
            float s[2][2][4];
#pragma unroll
            for (int m = 0; m < 2; m++)
#pragma unroll
                for (int j = 0; j < 2; j++)
#pragma unroll
                    for (int r = 0; r < 4; r++) s[m][j][r] = -C2F;

#pragma unroll
            for (int h = 0; h < 2; h++) {
                uint32_t kr[4];
                uint32_t addr = kbb
                    + (uint32_t)(kb + (mm >> 1) * 8 + mr) * 80
                    + (uint32_t)((mm & 1) * 16 + h * 32);
                ldsm4(kr, addr);
                mma_f16(s[0][0], qa[0][h], kr[0], kr[1]);
                mma_f16(s[0][1], qa[0][h], kr[2], kr[3]);
                mma_f16(s[1][0], qa[1][h], kr[0], kr[1]);
                mma_f16(s[1][1], qa[1][h], kr[2], kr[3]);
            }

            // ---- p = 2^s in fp16 pairs; C-frag == A-frag identity ----
            uint32_t aP[2][4];
#pragma unroll
            for (int m = 0; m < 2; m++) {
                aP[m][0] = h2ex2(f16x2(s[m][0][1], s[m][0][0]));
                aP[m][1] = h2ex2(f16x2(s[m][0][3], s[m][0][2]));
                aP[m][2] = h2ex2(f16x2(s[m][1][1], s[m][1][0]));
                aP[m][3] = h2ex2(f16x2(s[m][1][3], s[m][1][2]));
                float2 f0 = h2f2(hadd2(aP[m][0], aP[m][2]));
                float2 f1 = h2f2(hadd2(aP[m][1], aP[m][3]));
                lp[m][0] += f0.x + f0.y;
                lp[m][1] += f1.x + f1.y;
            }

            // ---- O += P·V via trans ldmatrix + fp16 MMA ----
#pragma unroll
            for (int h = 0; h < 2; h++) {
                uint32_t vr[4];
                uint32_t addr = vbb
                    + (uint32_t)(kb + (mm & 1) * 8 + mr) * 80
                    + (uint32_t)((mm >> 1) * 8 + h * 16) * 2;
                ldsm4t(vr, addr);
                mma_f16(oacc[0][2 * h],     aP[0], vr[0], vr[1]);
                mma_f16(oacc[0][2 * h + 1], aP[0], vr[2], vr[3]);
                mma_f16(oacc[1][2 * h],     aP[1], vr[0], vr[1]);
                mma_f16(oacc[1][2 * h + 1], aP[1], vr[2], vr[3]);
            }
        }
    }
    __syncthreads();   // all warps done with SMEM buffers

    // ---- combine key-halves via SMEM scratch ----
    float* sc = smf + wq * 1152;
    if (wk == 1) {
        int idx = 0;
#pragma unroll
        for (int m = 0; m < 2; m++)
#pragma unroll
            for (int n = 0; n < 4; n++)
#pragma unroll
                for (int r = 0; r < 4; r++)
                    sc[(idx++) * 32 + lane] = oacc[m][n][r];
#pragma unroll
        for (int m = 0; m < 2; m++)
#pragma unroll
            for (int r = 0; r < 2; r++)
                sc[1024 + (m * 2 + r) * 32 + lane] = lp[m][r];
    }
    __syncthreads();
    if (wk == 0) {
        int idx = 0;
#pragma unroll
        for (int m = 0; m < 2; m++)
#pragma unroll
            for (int n = 0; n < 4; n++)
#pragma unroll
                for (int r = 0; r < 4; r++)
                    oacc[m][n][r] += sc[(idx++) * 32 + lane];
#pragma unroll
        for (int m = 0; m < 2; m++)
#pragma unroll
            for (int r = 0; r < 2; r++)
                lp[m][r] += sc[1024 + (m * 2 + r) * 32 + lane];

#pragma unroll
        for (int m = 0; m < 2; m++)
#pragma unroll
            for (int r = 0; r < 2; r++) {
                float v = lp[m][r];
                v += __shfl_xor_sync(0xFFFFFFFFu, v, 1);
                v += __shfl_xor_sync(0xFFFFFFFFu, v, 2);
                lp[m][r] = 1.0f / v;
            }

        const int b  = bh >> 3;
        const int hh = bh & 7;
#pragma unroll
        for (int m = 0; m < 2; m++) {
            int q0 = qt * 128 + wq * 32 + m * 16 + gid;
#pragma unroll
            for (int n = 0; n < 4; n++) {
                int col = hh * 32 + n * 8 + 2 * tig;
                __half* p0 = Ch + (size_t)(b * N_ + q0) * D_ + col;
                __half* p1 = Ch + (size_t)(b * N_ + q0 + 8) * D_ + col;
                *(uint32_t*)p0 = f16x2(oacc[m][n][1] * lp[m][0],
                                       oacc[m][n][0] * lp[m][0]);
                *(uint32_t*)p1 = f16x2(oacc[m][n][3] * lp[m][1],
                                       oacc[m][n][2] * lp[m][1]);
            }
        }
    }
}

// ---------------------------------------------------------------------------
extern "C" void kernel_launch(void* const* d_in, const int* in_sizes, int n_in,
                              void* d_out, int out_size)
{
    const float* x  = (const float*)d_in[0];
    const float* Wq = (const float*)d_in[1];
    const float* bq = (const float*)d_in[2];
    const float* Wk = (const float*)d_in[3];
    const float* bk = (const float*)d_in[4];
    const float* Wv = (const float*)d_in[5];
    const float* bv = (const float*)d_in[6];
    const float* Wo = (const float*)d_in[7];
    const float* bo = (const float*)d_in[8];
    float* out = (float*)d_out;

    __half *qh, *kh, *vh, *xh, *wh, *ctxh;
    cudaGetSymbolAddress((void**)&qh,   g_qh_);
    cudaGetSymbolAddress((void**)&kh,   g_kh_);
    cudaGetSymbolAddress((void**)&vh,   g_vh_);
    cudaGetSymbolAddress((void**)&xh,   g_xh_);
    cudaGetSymbolAddress((void**)&wh,   g_wh_);
    cudaGetSymbolAddress((void**)&ctxh, g_ctxh_);

    cudaFuncSetAttribute(gemm_mma_kernel<1>,
                         cudaFuncAttributeMaxDynamicSharedMemorySize, GSM_BYTES);
    cudaFuncSetAttribute(gemm_mma_kernel<0>,
                         cudaFuncAttributeMaxDynamicSharedMemorySize, GSM_BYTES);
    cudaFuncSetAttribute(attn_mma_kernel,
                         cudaFuncAttributeMaxDynamicSharedMemorySize,
                         SMEM_ATTN_BYTES);

    cvt_kernel<<<296, 256>>>(x, Wq, Wk, Wv, Wo, xh, wh);

    dim3 qkv_grid(256 / 64, M_ / 64, 3);     // (4, 72, 3) = 864
    gemm_mma_kernel<1><<<qkv_grid, 256, GSM_BYTES>>>(
        xh, wh, bq, bk, bv, qh, kh, vh, nullptr);

    dim3 agrid(NTILE, BH_);                  // (18, 16)
    attn_mma_kernel<<<agrid, 256, SMEM_ATTN_BYTES>>>(qh, kh, vh, ctxh);

    dim3 o_grid(256 / 64, M_ / 64, 1);       // (4, 72, 1) = 288
    gemm_mma_kernel<0><<<o_grid, 256, GSM_BYTES>>>(
        ctxh, wh + 3 * D_ * D_, bo, bo, bo, nullptr, nullptr, nullptr, out);
}

// round 11
// speedup vs baseline: 1.0135x; 1.0135x over previous
#include <cuda_runtime.h>
#include <cuda_fp16.h>
#include <cstdint>

// ---------------------------------------------------------------------------
// TriangularAttention: B=2, S=48 -> N=2304, D=256, H=8, DH=32
// Round 11: GEMM cp.async pipeline deepened to 4 stages (3 chunks in flight,
//           always-commit group accounting). Attention unchanged from R9/R10.
// ---------------------------------------------------------------------------

constexpr int B_  = 2;
constexpr int S_  = 48;
constexpr int D_  = 256;
constexpr int H_  = 8;
constexpr int DH_ = 32;
constexpr int N_  = S_ * S_;     // 2304
constexpr int M_  = B_ * N_;     // 4608
constexpr int BH_ = B_ * H_;     // 16

// fp16 storage (uint4 for 16B alignment)
__device__ uint4 g_qh_[BH_ * N_ * DH_ / 8];
__device__ uint4 g_kh_[BH_ * N_ * DH_ / 8];
__device__ uint4 g_vh_[BH_ * N_ * DH_ / 8];
__device__ uint4 g_xh_[M_ * D_ / 8];
__device__ uint4 g_wh_[4 * D_ * D_ / 8];
__device__ uint4 g_ctxh_[M_ * D_ / 8];

// softmax: p = 2^(q·k·CS2 − C2); C2 cancels in the divide.
constexpr float CS2F = 0.17677669529663687f * 1.4426950408889634f;
constexpr float C2F  = 8.0f * 1.4426950408889634f;

// ---------------- helpers ---------------------------------------------------
__device__ __forceinline__ uint32_t f16x2(float hi, float lo) {  // {hi,lo}
    uint32_t r;
    asm("cvt.rn.f16x2.f32 %0, %1, %2;" : "=r"(r) : "f"(hi), "f"(lo));
    return r;
}
__device__ __forceinline__ uint32_t hadd2(uint32_t a, uint32_t b) {
    uint32_t d;
    asm("add.rn.f16x2 %0, %1, %2;" : "=r"(d) : "r"(a), "r"(b));
    return d;
}
__device__ __forceinline__ uint32_t h2ex2(uint32_t a) {
    uint32_t d;
    asm("ex2.approx.f16x2 %0, %1;" : "=r"(d) : "r"(a));
    return d;
}
__device__ __forceinline__ float2 h2f2(uint32_t h) {
    float lo, hi;
    asm("{ .reg .b16 l, m; mov.b32 {l, m}, %2;\n\t"
        "cvt.f32.f16 %0, l; cvt.f32.f16 %1, m; }"
        : "=f"(lo), "=f"(hi) : "r"(h));
    return make_float2(lo, hi);
}
__device__ __forceinline__ uint32_t smem_u32(const void* p) {
    uint32_t a;
    asm("{ .reg .u64 t; cvta.to.shared.u64 t, %1; cvt.u32.u64 %0, t; }"
        : "=r"(a) : "l"(p));
    return a;
}
__device__ __forceinline__ void mma_f16(float* d, const uint32_t* a,
                                        uint32_t b0, uint32_t b1) {
    asm volatile(
        "mma.sync.aligned.m16n8k16.row.col.f32.f16.f16.f32 "
        "{%0,%1,%2,%3}, {%4,%5,%6,%7}, {%8,%9}, {%0,%1,%2,%3};"
        : "+f"(d[0]), "+f"(d[1]), "+f"(d[2]), "+f"(d[3])
        : "r"(a[0]), "r"(a[1]), "r"(a[2]), "r"(a[3]), "r"(b0), "r"(b1));
}
__device__ __forceinline__ void ldsm4(uint32_t* r, uint32_t addr) {   // non-trans
    asm volatile(
        "ldmatrix.sync.aligned.m8n8.x4.shared.b16 {%0,%1,%2,%3}, [%4];"
        : "=r"(r[0]), "=r"(r[1]), "=r"(r[2]), "=r"(r[3]) : "r"(addr));
}
__device__ __forceinline__ void ldsm4t(uint32_t* r, uint32_t addr) {  // trans
    asm volatile(
        "ldmatrix.sync.aligned.m8n8.x4.trans.shared.b16 {%0,%1,%2,%3}, [%4];"
        : "=r"(r[0]), "=r"(r[1]), "=r"(r[2]), "=r"(r[3]) : "r"(addr));
}
__device__ __forceinline__ void cpa16(uint32_t dst, const void* src) {
    asm volatile("cp.async.cg.shared.global [%0], [%1], 16;"
                 :: "r"(dst), "l"(src));
}
__device__ __forceinline__ void cp_commit() {
    asm volatile("cp.async.commit_group;");
}
template <int NWAIT>
__device__ __forceinline__ void cp_wait() {
    asm volatile("cp.async.wait_group %0;" :: "n"(NWAIT));
}

// ---------------------------------------------------------------------------
// One-shot fp32 -> fp16 conversion: x and all four weight matrices.
// ---------------------------------------------------------------------------
__global__ __launch_bounds__(256) void cvt_kernel(
    const float* __restrict__ x,
    const float* __restrict__ Wq, const float* __restrict__ Wk,
    const float* __restrict__ Wv, const float* __restrict__ Wo,
    __half* __restrict__ xh, __half* __restrict__ wh)
{
    const int tid    = blockIdx.x * 256 + threadIdx.x;
    const int stride = gridDim.x * 256;
    auto seg = [&](const float* s, __half* d, int n4) {
        for (int i = tid; i < n4; i += stride) {
            float4 v = ((const float4*)s)[i];
            uint2 h;
            h.x = f16x2(v.y, v.x);
            h.y = f16x2(v.w, v.z);
            ((uint2*)d)[i] = h;
        }
    };
    seg(x,  xh,                M_ * D_ / 4);
    seg(Wq, wh,                D_ * D_ / 4);
    seg(Wk, wh + D_ * D_,      D_ * D_ / 4);
    seg(Wv, wh + 2 * D_ * D_,  D_ * D_ / 4);
    seg(Wo, wh + 3 * D_ * D_,  D_ * D_ / 4);
}

// ---------------------------------------------------------------------------
// fp16 GEMM, 64x64 CTA tile, 4-stage cp.async pipeline.
// out[M,256] = A[M,256] @ W[256,256] + bias.
// 8 warps (2 row x 4 col), k-chunks of 32.
// A [row][k] 80B stride (ldsm -> A-frag); W [k][c] 144B stride (ldsm.trans).
// QKV=1: three fp16 head-major outputs (z selects), q scaled by CS2.
// QKV=0: single f32 row-major output.
// ---------------------------------------------------------------------------
constexpr int GA_BYTES = 64 * 80;     // 5120
constexpr int GW_BYTES = 32 * 144;    // 4608
constexpr int GST_BYTES = GA_BYTES + GW_BYTES;      // 9728 per stage
constexpr int GSM_BYTES = 4 * GST_BYTES;            // 38912

template <int QKV>
__global__ __launch_bounds__(256) void gemm_mma_kernel(
    const __half* __restrict__ Ah, const __half* __restrict__ Whb,
    const float* __restrict__ bias0, const float* __restrict__ bias1,
    const float* __restrict__ bias2,
    __half* __restrict__ o0h, __half* __restrict__ o1h,
    __half* __restrict__ o2h, float* __restrict__ outf)
{
    extern __shared__ __align__(16) char smc[];

    const int z = blockIdx.z;
    const __half* W   = Whb + (size_t)z * D_ * D_;
    const float* bias = (z == 0) ? bias0 : (z == 1) ? bias1 : bias2;
    __half* oh        = (z == 0) ? o0h : (z == 1) ? o1h : o2h;
    const float sc    = (QKV && z == 0) ? CS2F : 1.0f;

    const int tid  = threadIdx.x;
    const int warp = tid >> 5;
    const int lane = tid & 31;
    const int gid  = lane >> 2;
    const int tig  = lane & 3;
    const int wr   = warp & 1;          // 2 row groups of 32
    const int wc   = warp >> 1;         // 4 col groups of 16
    const int c0   = blockIdx.x * 64;
    const int m0   = blockIdx.y * 64;
    const int mm   = lane >> 3;
    const int mr   = lane & 7;

    const uint32_t sb = smem_u32(smc);

    float acc[2][2][4];
#pragma unroll
    for (int m = 0; m < 2; m++)
#pragma unroll
        for (int n = 0; n < 2; n++)
#pragma unroll
            for (int r = 0; r < 4; r++) acc[m][n][r] = 0.f;

    auto load_chunk = [&](int k0, int buf) {
        uint32_t as = sb + buf * GST_BYTES;
        uint32_t ws = as + GA_BYTES;
        const char* Ab = (const char*)Ah + ((size_t)m0 * 256 + k0) * 2;
        const char* Wb = (const char*)W + ((size_t)k0 * 256 + c0) * 2;
        {
            int row = tid >> 2, c = tid & 3;       // 64 rows x 4 x 16B
            cpa16(as + row * 80 + c * 16, Ab + (size_t)row * 512 + c * 16);
        }
        {
            int kk = tid >> 3, c8 = tid & 7;       // 32 k x 8 x 16B
            cpa16(ws + kk * 144 + c8 * 16, Wb + (size_t)kk * 512 + c8 * 16);
        }
    };

    // Prologue: 3 chunks in flight.
    load_chunk(0, 0);  cp_commit();
    load_chunk(32, 1); cp_commit();
    load_chunk(64, 2); cp_commit();

#pragma unroll 1
    for (int kc = 0; kc < 8; kc++) {
        const int buf = kc & 3;
        cp_wait<2>();          // chunk kc resident (2 youngest groups pending)
        __syncthreads();

        const uint32_t as = sb + buf * GST_BYTES;
        const uint32_t ws = as + GA_BYTES;

#pragma unroll
        for (int h = 0; h < 2; h++) {
            uint32_t a[2][4];
#pragma unroll
            for (int mt = 0; mt < 2; mt++) {
                uint32_t addr = as
                    + (uint32_t)(wr * 32 + mt * 16 + (mm & 1) * 8 + mr) * 80
                    + (uint32_t)(h * 32 + (mm >> 1) * 16);
                ldsm4(a[mt], addr);
            }
            uint32_t w[4];
            {
                uint32_t addr = ws
                    + (uint32_t)(h * 16 + (mm & 1) * 8 + mr) * 144
                    + (uint32_t)(wc * 16 + (mm >> 1) * 8) * 2;
                ldsm4t(w, addr);
            }
            mma_f16(acc[0][0], a[0], w[0], w[1]);
            mma_f16(acc[0][1], a[0], w[2], w[3]);
            mma_f16(acc[1][0], a[1], w[0], w[1]);
            mma_f16(acc[1][1], a[1], w[2], w[3]);
        }

        // Refill: buf (kc+3)&3 was consumed in iter kc-1; all threads passed
        // the barrier above after that, so overwrite is safe. Always commit
        // (empty groups near the tail keep the wait<2> accounting uniform).
        if (kc + 3 < 8) load_chunk((kc + 3) * 32, (kc + 3) & 3);
        cp_commit();
    }

#pragma unroll
    for (int n = 0; n < 2; n++) {
        int c = c0 + wc * 16 + n * 8 + 2 * tig;
        float bv0 = bias[c], bv1 = bias[c + 1];
#pragma unroll
        for (int m = 0; m < 2; m++) {
            int row = m0 + wr * 32 + m * 16 + gid;
            if (QKV) {
                int hh = c >> 5;
                int dh = c & 31;
                int b  = row / N_;
                int nn = row - b * N_;
                __half* p = oh + (((size_t)(b * H_ + hh)) * N_ + nn) * DH_ + dh;
                *(uint32_t*)p = f16x2((acc[m][n][1] + bv1) * sc,
                                      (acc[m][n][0] + bv0) * sc);
                *(uint32_t*)(p + 8 * DH_) = f16x2((acc[m][n][3] + bv1) * sc,
                                                  (acc[m][n][2] + bv0) * sc);
            } else {
                float* p = outf + (size_t)row * 256 + c;
                *(float2*)p = make_float2(acc[m][n][0] + bv0, acc[m][n][1] + bv1);
                *(float2*)(p + 8 * 256) =
                    make_float2(acc[m][n][2] + bv0, acc[m][n][3] + bv1);
            }
        }
    }
}

// ---------------------------------------------------------------------------
// fp16 flash attention (unchanged from round 9/10).
// ---------------------------------------------------------------------------
constexpr int NTILE = N_ / 128;   // 18
constexpr int KB0 = 0;
constexpr int KB1 = 128 * 80;     // 10240
constexpr int VB0 = 2 * 128 * 80;
constexpr int VB1 = VB0 + 128 * 80;
constexpr int SMEM_ATTN_BYTES = VB1 + 128 * 80;  // 40960

__global__ __launch_bounds__(256, 2) void attn_mma_kernel(
    const __half* __restrict__ Qh, const __half* __restrict__ Kh,
    const __half* __restrict__ Vh, __half* __restrict__ Ch)
{
    extern __shared__ __align__(16) float smf[];
    const int tid  = threadIdx.x;
    const int warp = tid >> 5;
    const int lane = tid & 31;
    const int gid  = lane >> 2;
    const int tig  = lane & 3;
    const int wq   = warp & 3;
    const int wk   = warp >> 2;
    const int bh   = blockIdx.y;
    const int qt   = blockIdx.x;
    const int mm   = lane >> 3;
    const int mr   = lane & 7;

    const uint32_t sb = smem_u32(smf);

    const __half* Qg = Qh + ((size_t)bh * N_ + qt * 128) * DH_;
    const __half* Kg = Kh + (size_t)bh * N_ * DH_;
    const __half* Vg = Vh + (size_t)bh * N_ * DH_;

    // ---- Q fp16 A-frags (pre-scaled at projection): direct uint loads ----
    uint32_t qa[2][2][4];
#pragma unroll
    for (int m = 0; m < 2; m++) {
        const __half* r0 = Qg + (size_t)(wq * 32 + m * 16 + gid) * DH_;
        const __half* r1 = r0 + 8 * DH_;
#pragma unroll
        for (int h = 0; h < 2; h++) {
            int k0 = h * 16 + 2 * tig;
            qa[m][h][0] = *(const uint32_t*)(r0 + k0);
            qa[m][h][1] = *(const uint32_t*)(r1 + k0);
            qa[m][h][2] = *(const uint32_t*)(r0 + k0 + 8);
            qa[m][h][3] = *(const uint32_t*)(r1 + k0 + 8);
        }
    }

    float oacc[2][4][4];
#pragma unroll
    for (int m = 0; m < 2; m++)
#pragma unroll
        for (int n = 0; n < 4; n++)
#pragma unroll
            for (int r = 0; r < 4; r++) oacc[m][n][r] = 0.f;
    float lp[2][2] = {{0.f, 0.f}, {0.f, 0.f}};

    // ---- cp.async tile loader: K,V 128 x 64B rows -> 80B stride SMEM ----
    auto load_tile = [&](int t, int buf) {
        uint32_t kd = sb + (buf ? KB1 : KB0);
        uint32_t vd = sb + (buf ? VB1 : VB0);
        const char* ks = (const char*)(Kg + (size_t)t * 128 * DH_);
        const char* vs = (const char*)(Vg + (size_t)t * 128 * DH_);
#pragma unroll
        for (int r = 0; r < 2; r++) {
            int idx = tid + r * 256;           // 0..511
            int row = idx >> 2, c = idx & 3;
            cpa16(kd + row * 80 + c * 16, ks + (size_t)row * 64 + c * 16);
            cpa16(vd + row * 80 + c * 16, vs + (size_t)row * 64 + c * 16);
        }
    };

    load_tile(0, 0);
    cp_commit();

    for (int t = 0; t < NTILE; t++) {
        const int buf = t & 1;
        cp_wait<0>();
        __syncthreads();
        if (t + 1 < NTILE) {
            load_tile(t + 1, buf ^ 1);
            cp_commit();
        }

        const uint32_t kbb = sb + (buf ? KB1 : KB0);
        const uint32_t vbb = sb + (buf ? VB1 : VB0);

#pragma unroll
        for (int g = 0; g < 4; g++) {
            const int kb = wk * 64 + g * 16;

            // ---- S = (scaled Q)·K^T − C2, fp16 MMA ----
            float s[2][2][4];
#pragma unroll
            for (int m = 0; m < 2; m++)
#pragma unroll
                for (int j = 0; j < 2; j++)
#pragma unroll
                    for (int r = 0; r < 4; r++) s[m][j][r] = -C2F;

#pragma unroll
            for (int h = 0; h < 2; h++) {
                uint32_t kr[4];
                uint32_t addr = kbb
                    + (uint32_t)(kb + (mm >> 1) * 8 + mr) * 80
                    + (uint32_t)((mm & 1) * 16 + h * 32);
                ldsm4(kr, addr);
                mma_f16(s[0][0], qa[0][h], kr[0], kr[1]);
                mma_f16(s[0][1], qa[0][h], kr[2], kr[3]);
                mma_f16(s[1][0], qa[1][h], kr[0], kr[1]);
                mma_f16(s[1][1], qa[1][h], kr[2], kr[3]);
            }

            // ---- p = 2^s in fp16 pairs; C-frag == A-frag identity ----
            uint32_t aP[2][4];
#pragma unroll
            for (int m = 0; m < 2; m++) {
                aP[m][0] = h2ex2(f16x2(s[m][0][1], s[m][0][0]));
                aP[m][1] = h2ex2(f16x2(s[m][0][3], s[m][0][2]));
                aP[m][2] = h2ex2(f16x2(s[m][1][1], s[m][1][0]));
                aP[m][3] = h2ex2(f16x2(s[m][1][3], s[m][1][2]));
                float2 f0 = h2f2(hadd2(aP[m][0], aP[m][2]));
                float2 f1 = h2f2(hadd2(aP[m][1], aP[m][3]));
                lp[m][0] += f0.x + f0.y;
                lp[m][1] += f1.x + f1.y;
            }

            // ---- O += P·V via trans ldmatrix + fp16 MMA ----
#pragma unroll
            for (int h = 0; h < 2; h++) {
                uint32_t vr[4];
                uint32_t addr = vbb
                    + (uint32_t)(kb + (mm & 1) * 8 + mr) * 80
                    + (uint32_t)((mm >> 1) * 8 + h * 16) * 2;
                ldsm4t(vr, addr);
                mma_f16(oacc[0][2 * h],     aP[0], vr[0], vr[1]);
                mma_f16(oacc[0][2 * h + 1], aP[0], vr[2], vr[3]);
                mma_f16(oacc[1][2 * h],     aP[1], vr[0], vr[1]);
                mma_f16(oacc[1][2 * h + 1], aP[1], vr[2], vr[3]);
            }
        }
    }
    __syncthreads();   // all warps done with SMEM buffers

    // ---- combine key-halves via SMEM scratch ----
    float* sc = smf + wq * 1152;
    if (wk == 1) {
        int idx = 0;
#pragma unroll
        for (int m = 0; m < 2; m++)
#pragma unroll
            for (int n = 0; n < 4; n++)
#pragma unroll
                for (int r = 0; r < 4; r++)
                    sc[(idx++) * 32 + lane] = oacc[m][n][r];
#pragma unroll
        for (int m = 0; m < 2; m++)
#pragma unroll
            for (int r = 0; r < 2; r++)
                sc[1024 + (m * 2 + r) * 32 + lane] = lp[m][r];
    }
    __syncthreads();
    if (wk == 0) {
        int idx = 0;
#pragma unroll
        for (int m = 0; m < 2; m++)
#pragma unroll
            for (int n = 0; n < 4; n++)
#pragma unroll
                for (int r = 0; r < 4; r++)
                    oacc[m][n][r] += sc[(idx++) * 32 + lane];
#pragma unroll
        for (int m = 0; m < 2; m++)
#pragma unroll
            for (int r = 0; r < 2; r++)
                lp[m][r] += sc[1024 + (m * 2 + r) * 32 + lane];

#pragma unroll
        for (int m = 0; m < 2; m++)
#pragma unroll
            for (int r = 0; r < 2; r++) {
                float v = lp[m][r];
                v += __shfl_xor_sync(0xFFFFFFFFu, v, 1);
                v += __shfl_xor_sync(0xFFFFFFFFu, v, 2);
                lp[m][r] = 1.0f / v;
            }

        const int b  = bh >> 3;
        const int hh = bh & 7;
#pragma unroll
        for (int m = 0; m < 2; m++) {
            int q0 = qt * 128 + wq * 32 + m * 16 + gid;
#pragma unroll
            for (int n = 0; n < 4; n++) {
                int col = hh * 32 + n * 8 + 2 * tig;
                __half* p0 = Ch + (size_t)(b * N_ + q0) * D_ + col;
                __half* p1 = Ch + (size_t)(b * N_ + q0 + 8) * D_ + col;
                *(uint32_t*)p0 = f16x2(oacc[m][n][1] * lp[m][0],
                                       oacc[m][n][0] * lp[m][0]);
                *(uint32_t*)p1 = f16x2(oacc[m][n][3] * lp[m][1],
                                       oacc[m][n][2] * lp[m][1]);
            }
        }
    }
}

// ---------------------------------------------------------------------------
extern "C" void kernel_launch(void* const* d_in, const int* in_sizes, int n_in,
                              void* d_out, int out_size)
{
    const float* x  = (const float*)d_in[0];
    const float* Wq = (const float*)d_in[1];
    const float* bq = (const float*)d_in[2];
    const float* Wk = (const float*)d_in[3];
    const float* bk = (const float*)d_in[4];
    const float* Wv = (const float*)d_in[5];
    const float* bv = (const float*)d_in[6];
    const float* Wo = (const float*)d_in[7];
    const float* bo = (const float*)d_in[8];
    float* out = (float*)d_out;

    __half *qh, *kh, *vh, *xh, *wh, *ctxh;
    cudaGetSymbolAddress((void**)&qh,   g_qh_);
    cudaGetSymbolAddress((void**)&kh,   g_kh_);
    cudaGetSymbolAddress((void**)&vh,   g_vh_);
    cudaGetSymbolAddress((void**)&xh,   g_xh_);
    cudaGetSymbolAddress((void**)&wh,   g_wh_);
    cudaGetSymbolAddress((void**)&ctxh, g_ctxh_);

    cudaFuncSetAttribute(gemm_mma_kernel<1>,
                         cudaFuncAttributeMaxDynamicSharedMemorySize, GSM_BYTES);
    cudaFuncSetAttribute(gemm_mma_kernel<0>,
                         cudaFuncAttributeMaxDynamicSharedMemorySize, GSM_BYTES);
    cudaFuncSetAttribute(attn_mma_kernel,
                         cudaFuncAttributeMaxDynamicSharedMemorySize,
                         SMEM_ATTN_BYTES);

    cvt_kernel<<<296, 256>>>(x, Wq, Wk, Wv, Wo, xh, wh);

    dim3 qkv_grid(256 / 64, M_ / 64, 3);     // (4, 72, 3) = 864
    gemm_mma_kernel<1><<<qkv_grid, 256, GSM_BYTES>>>(
        xh, wh, bq, bk, bv, qh, kh, vh, nullptr);

    dim3 agrid(NTILE, BH_);                  // (18, 16)
    attn_mma_kernel<<<agrid, 256, SMEM_ATTN_BYTES>>>(qh, kh, vh, ctxh);

    dim3 o_grid(256 / 64, M_ / 64, 1);       // (4, 72, 1) = 288
    gemm_mma_kernel<0><<<o_grid, 256, GSM_BYTES>>>(
        ctxh, wh + 3 * D_ * D_, bo, bo, bo, nullptr, nullptr, nullptr, out);
}

// round 12
// speedup vs baseline: 1.0326x; 1.0189x over previous
#include <cuda_runtime.h>
#include <cuda_fp16.h>
#include <cstdint>

// ---------------------------------------------------------------------------
// TriangularAttention: B=2, S=48 -> N=2304, D=256, H=8, DH=32
// Round 12: GEMMs use full-K SMEM residency (one cp.async phase, one barrier,
//           16 barrier-free k-steps). Attention unchanged from R9-R11.
// ---------------------------------------------------------------------------

constexpr int B_  = 2;
constexpr int S_  = 48;
constexpr int D_  = 256;
constexpr int H_  = 8;
constexpr int DH_ = 32;
constexpr int N_  = S_ * S_;     // 2304
constexpr int M_  = B_ * N_;     // 4608
constexpr int BH_ = B_ * H_;     // 16

// fp16 storage (uint4 for 16B alignment)
__device__ uint4 g_qh_[BH_ * N_ * DH_ / 8];
__device__ uint4 g_kh_[BH_ * N_ * DH_ / 8];
__device__ uint4 g_vh_[BH_ * N_ * DH_ / 8];
__device__ uint4 g_xh_[M_ * D_ / 8];
__device__ uint4 g_wh_[4 * D_ * D_ / 8];
__device__ uint4 g_ctxh_[M_ * D_ / 8];

// softmax: p = 2^(q·k·CS2 − C2); C2 cancels in the divide.
constexpr float CS2F = 0.17677669529663687f * 1.4426950408889634f;
constexpr float C2F  = 8.0f * 1.4426950408889634f;

// ---------------- helpers ---------------------------------------------------
__device__ __forceinline__ uint32_t f16x2(float hi, float lo) {  // {hi,lo}
    uint32_t r;
    asm("cvt.rn.f16x2.f32 %0, %1, %2;" : "=r"(r) : "f"(hi), "f"(lo));
    return r;
}
__device__ __forceinline__ uint32_t hadd2(uint32_t a, uint32_t b) {
    uint32_t d;
    asm("add.rn.f16x2 %0, %1, %2;" : "=r"(d) : "r"(a), "r"(b));
    return d;
}
__device__ __forceinline__ uint32_t h2ex2(uint32_t a) {
    uint32_t d;
    asm("ex2.approx.f16x2 %0, %1;" : "=r"(d) : "r"(a));
    return d;
}
__device__ __forceinline__ float2 h2f2(uint32_t h) {
    float lo, hi;
    asm("{ .reg .b16 l, m; mov.b32 {l, m}, %2;\n\t"
        "cvt.f32.f16 %0, l; cvt.f32.f16 %1, m; }"
        : "=f"(lo), "=f"(hi) : "r"(h));
    return make_float2(lo, hi);
}
__device__ __forceinline__ uint32_t smem_u32(const void* p) {
    uint32_t a;
    asm("{ .reg .u64 t; cvta.to.shared.u64 t, %1; cvt.u32.u64 %0, t; }"
        : "=r"(a) : "l"(p));
    return a;
}
__device__ __forceinline__ void mma_f16(float* d, const uint32_t* a,
                                        uint32_t b0, uint32_t b1) {
    asm volatile(
        "mma.sync.aligned.m16n8k16.row.col.f32.f16.f16.f32 "
        "{%0,%1,%2,%3}, {%4,%5,%6,%7}, {%8,%9}, {%0,%1,%2,%3};"
        : "+f"(d[0]), "+f"(d[1]), "+f"(d[2]), "+f"(d[3])
        : "r"(a[0]), "r"(a[1]), "r"(a[2]), "r"(a[3]), "r"(b0), "r"(b1));
}
__device__ __forceinline__ void ldsm4(uint32_t* r, uint32_t addr) {   // non-trans
    asm volatile(
        "ldmatrix.sync.aligned.m8n8.x4.shared.b16 {%0,%1,%2,%3}, [%4];"
        : "=r"(r[0]), "=r"(r[1]), "=r"(r[2]), "=r"(r[3]) : "r"(addr));
}
__device__ __forceinline__ void ldsm4t(uint32_t* r, uint32_t addr) {  // trans
    asm volatile(
        "ldmatrix.sync.aligned.m8n8.x4.trans.shared.b16 {%0,%1,%2,%3}, [%4];"
        : "=r"(r[0]), "=r"(r[1]), "=r"(r[2]), "=r"(r[3]) : "r"(addr));
}
__device__ __forceinline__ void cpa16(uint32_t dst, const void* src) {
    asm volatile("cp.async.cg.shared.global [%0], [%1], 16;"
                 :: "r"(dst), "l"(src));
}
__device__ __forceinline__ void cp_commit() {
    asm volatile("cp.async.commit_group;");
}
template <int NWAIT>
__device__ __forceinline__ void cp_wait() {
    asm volatile("cp.async.wait_group %0;" :: "n"(NWAIT));
}

// ---------------------------------------------------------------------------
// One-shot fp32 -> fp16 conversion: x and all four weight matrices.
// ---------------------------------------------------------------------------
__global__ __launch_bounds__(256) void cvt_kernel(
    const float* __restrict__ x,
    const float* __restrict__ Wq, const float* __restrict__ Wk,
    const float* __restrict__ Wv, const float* __restrict__ Wo,
    __half* __restrict__ xh, __half* __restrict__ wh)
{
    const int tid    = blockIdx.x * 256 + threadIdx.x;
    const int stride = gridDim.x * 256;
    auto seg = [&](const float* s, __half* d, int n4) {
        for (int i = tid; i < n4; i += stride) {
            float4 v = ((const float4*)s)[i];
            uint2 h;
            h.x = f16x2(v.y, v.x);
            h.y = f16x2(v.w, v.z);
            ((uint2*)d)[i] = h;
        }
    };
    seg(x,  xh,                M_ * D_ / 4);
    seg(Wq, wh,                D_ * D_ / 4);
    seg(Wk, wh + D_ * D_,      D_ * D_ / 4);
    seg(Wv, wh + 2 * D_ * D_,  D_ * D_ / 4);
    seg(Wo, wh + 3 * D_ * D_,  D_ * D_ / 4);
}

// ---------------------------------------------------------------------------
// fp16 GEMM, 64x64 CTA tile, FULL-K residency (K=256 in SMEM at once).
// One cp.async phase (16 per thread), one wait+barrier, then 16 k-steps of
// pure ldsm+MMA. 8 warps (2 row x 4 col).
// A [row][k] 528B stride (ldsm -> A-frag); W [k][c] 144B stride (ldsm.trans).
// QKV=1: three fp16 head-major outputs (z selects), q scaled by CS2.
// QKV=0: single f32 row-major output.
// ---------------------------------------------------------------------------
constexpr int AST = 528;                      // A row stride (512B data + 16 pad)
constexpr int WST = 144;                      // W row stride (128B data + 16 pad)
constexpr int GA_BYTES = 64 * AST;            // 33792
constexpr int GW_BYTES = 256 * WST;           // 36864
constexpr int GSM_BYTES = GA_BYTES + GW_BYTES;// 70656

template <int QKV>
__global__ __launch_bounds__(256) void gemm_mma_kernel(
    const __half* __restrict__ Ah, const __half* __restrict__ Whb,
    const float* __restrict__ bias0, const float* __restrict__ bias1,
    const float* __restrict__ bias2,
    __half* __restrict__ o0h, __half* __restrict__ o1h,
    __half* __restrict__ o2h, float* __restrict__ outf)
{
    extern __shared__ __align__(16) char smc[];

    const int z = blockIdx.z;
    const __half* W   = Whb + (size_t)z * D_ * D_;
    const float* bias = (z == 0) ? bias0 : (z == 1) ? bias1 : bias2;
    __half* oh        = (z == 0) ? o0h : (z == 1) ? o1h : o2h;
    const float sc    = (QKV && z == 0) ? CS2F : 1.0f;

    const int tid  = threadIdx.x;
    const int warp = tid >> 5;
    const int lane = tid & 31;
    const int gid  = lane >> 2;
    const int tig  = lane & 3;
    const int wr   = warp & 1;          // 2 row groups of 32
    const int wc   = warp >> 1;         // 4 col groups of 16
    const int c0   = blockIdx.x * 64;
    const int m0   = blockIdx.y * 64;
    const int mm   = lane >> 3;
    const int mr   = lane & 7;

    const uint32_t sb = smem_u32(smc);
    const uint32_t ws = sb + GA_BYTES;

    // ---- single load phase: entire 64x256 A slab + 256x64 W slab ----
    {
        const char* Ab = (const char*)(Ah + (size_t)m0 * 256);
        const char* Wb = (const char*)(W + c0);
#pragma unroll
        for (int r = 0; r < 8; r++) {          // A: 64 rows x 32 chunks
            int idx = tid + r * 256;
            int row = idx >> 5, c = idx & 31;
            cpa16(sb + row * AST + c * 16, Ab + (size_t)row * 512 + c * 16);
        }
#pragma unroll
        for (int r = 0; r < 8; r++) {          // W: 256 rows x 8 chunks
            int idx = tid + r * 256;
            int row = idx >> 3, c = idx & 7;
            cpa16(ws + row * WST + c * 16, Wb + (size_t)row * 512 + c * 16);
        }
    }
    cp_commit();

    float acc[2][2][4];
#pragma unroll
    for (int m = 0; m < 2; m++)
#pragma unroll
        for (int n = 0; n < 2; n++)
#pragma unroll
            for (int r = 0; r < 4; r++) acc[m][n][r] = 0.f;

    cp_wait<0>();
    __syncthreads();

    // ---- 16 k-steps, zero barriers ----
#pragma unroll
    for (int h = 0; h < 16; h++) {
        uint32_t a[2][4];
#pragma unroll
        for (int mt = 0; mt < 2; mt++) {
            uint32_t addr = sb
                + (uint32_t)(wr * 32 + mt * 16 + (mm & 1) * 8 + mr) * AST
                + (uint32_t)(h * 32 + (mm >> 1) * 16);
            ldsm4(a[mt], addr);
        }
        uint32_t w[4];
        {
            uint32_t addr = ws
                + (uint32_t)(h * 16 + (mm & 1) * 8 + mr) * WST
                + (uint32_t)(wc * 16 + (mm >> 1) * 8) * 2;
            ldsm4t(w, addr);
        }
        mma_f16(acc[0][0], a[0], w[0], w[1]);
        mma_f16(acc[0][1], a[0], w[2], w[3]);
        mma_f16(acc[1][0], a[1], w[0], w[1]);
        mma_f16(acc[1][1], a[1], w[2], w[3]);
    }

    // ---- epilogue ----
#pragma unroll
    for (int n = 0; n < 2; n++) {
        int c = c0 + wc * 16 + n * 8 + 2 * tig;
        float bv0 = bias[c], bv1 = bias[c + 1];
#pragma unroll
        for (int m = 0; m < 2; m++) {
            int row = m0 + wr * 32 + m * 16 + gid;
            if (QKV) {
                int hh = c >> 5;
                int dh = c & 31;
                int b  = row / N_;
                int nn = row - b * N_;
                __half* p = oh + (((size_t)(b * H_ + hh)) * N_ + nn) * DH_ + dh;
                *(uint32_t*)p = f16x2((acc[m][n][1] + bv1) * sc,
                                      (acc[m][n][0] + bv0) * sc);
                *(uint32_t*)(p + 8 * DH_) = f16x2((acc[m][n][3] + bv1) * sc,
                                                  (acc[m][n][2] + bv0) * sc);
            } else {
                float* p = outf + (size_t)row * 256 + c;
                *(float2*)p = make_float2(acc[m][n][0] + bv0, acc[m][n][1] + bv1);
                *(float2*)(p + 8 * 256) =
                    make_float2(acc[m][n][2] + bv0, acc[m][n][3] + bv1);
            }
        }
    }
}

// ---------------------------------------------------------------------------
// fp16 flash attention (unchanged from rounds 9-11).
// ---------------------------------------------------------------------------
constexpr int NTILE = N_ / 128;   // 18
constexpr int KB0 = 0;
constexpr int KB1 = 128 * 80;     // 10240
constexpr int VB0 = 2 * 128 * 80;
constexpr int VB1 = VB0 + 128 * 80;
constexpr int SMEM_ATTN_BYTES = VB1 + 128 * 80;  // 40960

__global__ __launch_bounds__(256, 2) void attn_mma_kernel(
    const __half* __restrict__ Qh, const __half* __restrict__ Kh,
    const __half* __restrict__ Vh, __half* __restrict__ Ch)
{
    extern __shared__ __align__(16) float smf[];
    const int tid  = threadIdx.x;
    const int warp = tid >> 5;
    const int lane = tid & 31;
    const int gid  = lane >> 2;
    const int tig  = lane & 3;
    const int wq   = warp & 3;
    const int wk   = warp >> 2;
    const int bh   = blockIdx.y;
    const int qt   = blockIdx.x;
    const int mm   = lane >> 3;
    const int mr   = lane & 7;

    const uint32_t sb = smem_u32(smf);

    const __half* Qg = Qh + ((size_t)bh * N_ + qt * 128) * DH_;
    const __half* Kg = Kh + (size_t)bh * N_ * DH_;
    const __half* Vg = Vh + (size_t)bh * N_ * DH_;

    // ---- Q fp16 A-frags (pre-scaled at projection): direct uint loads ----
    uint32_t qa[2][2][4];
#pragma unroll
    for (int m = 0; m < 2; m++) {
        const __half* r0 = Qg + (size_t)(wq * 32 + m * 16 + gid) * DH_;
        const __half* r1 = r0 + 8 * DH_;
#pragma unroll
        for (int h = 0; h < 2; h++) {
            int k0 = h * 16 + 2 * tig;
            qa[m][h][0] = *(const uint32_t*)(r0 + k0);
            qa[m][h][1] = *(const uint32_t*)(r1 + k0);
            qa[m][h][2] = *(const uint32_t*)(r0 + k0 + 8);
            qa[m][h][3] = *(const uint32_t*)(r1 + k0 + 8);
        }
    }

    float oacc[2][4][4];
#pragma unroll
    for (int m = 0; m < 2; m++)
#pragma unroll
        for (int n = 0; n < 4; n++)
#pragma unroll
            for (int r = 0; r < 4; r++) oacc[m][n][r] = 0.f;
    float lp[2][2] = {{0.f, 0.f}, {0.f, 0.f}};

    // ---- cp.async tile loader: K,V 128 x 64B rows -> 80B stride SMEM ----
    auto load_tile = [&](int t, int buf) {
        uint32_t kd = sb + (buf ? KB1 : KB0);
        uint32_t vd = sb + (buf ? VB1 : VB0);
        const char* ks = (const char*)(Kg + (size_t)t * 128 * DH_);
        const char* vs = (const char*)(Vg + (size_t)t * 128 * DH_);
#pragma unroll
        for (int r = 0; r < 2; r++) {
            int idx = tid + r * 256;           // 0..511
            int row = idx >> 2, c = idx & 3;
            cpa16(kd + row * 80 + c * 16, ks + (size_t)row * 64 + c * 16);
            cpa16(vd + row * 80 + c * 16, vs + (size_t)row * 64 + c * 16);
        }
    };

    load_tile(0, 0);
    cp_commit();

    for (int t = 0; t < NTILE; t++) {
        const int buf = t & 1;
        cp_wait<0>();
        __syncthreads();
        if (t + 1 < NTILE) {
            load_tile(t + 1, buf ^ 1);
            cp_commit();
        }

        const uint32_t kbb = sb + (buf ? KB1 : KB0);
        const uint32_t vbb = sb + (buf ? VB1 : VB0);

#pragma unroll
        for (int g = 0; g < 4; g++) {
            const int kb = wk * 64 + g * 16;

            // ---- S = (scaled Q)·K^T − C2, fp16 MMA ----
            float s[2][2][4];
#pragma unroll
            for (int m = 0; m < 2; m++)
#pragma unroll
                for (int j = 0; j < 2; j++)
#pragma unroll
                    for (int r = 0; r < 4; r++) s[m][j][r] = -C2F;

#pragma unroll
            for (int h = 0; h < 2; h++) {
                uint32_t kr[4];
                uint32_t addr = kbb
                    + (uint32_t)(kb + (mm >> 1) * 8 + mr) * 80
                    + (uint32_t)((mm & 1) * 16 + h * 32);
                ldsm4(kr, addr);
                mma_f16(s[0][0], qa[0][h], kr[0], kr[1]);
                mma_f16(s[0][1], qa[0][h], kr[2], kr[3]);
                mma_f16(s[1][0], qa[1][h], kr[0], kr[1]);
                mma_f16(s[1][1], qa[1][h], kr[2], kr[3]);
            }

            // ---- p = 2^s in fp16 pairs; C-frag == A-frag identity ----
            uint32_t aP[2][4];
#pragma unroll
            for (int m = 0; m < 2; m++) {
                aP[m][0] = h2ex2(f16x2(s[m][0][1], s[m][0][0]));
                aP[m][1] = h2ex2(f16x2(s[m][0][3], s[m][0][2]));
                aP[m][2] = h2ex2(f16x2(s[m][1][1], s[m][1][0]));
                aP[m][3] = h2ex2(f16x2(s[m][1][3], s[m][1][2]));
                float2 f0 = h2f2(hadd2(aP[m][0], aP[m][2]));
                float2 f1 = h2f2(hadd2(aP[m][1], aP[m][3]));
                lp[m][0] += f0.x + f0.y;
                lp[m][1] += f1.x + f1.y;
            }

            // ---- O += P·V via trans ldmatrix + fp16 MMA ----
#pragma unroll
            for (int h = 0; h < 2; h++) {
                uint32_t vr[4];
                uint32_t addr = vbb
                    + (uint32_t)(kb + (mm & 1) * 8 + mr) * 80
                    + (uint32_t)((mm >> 1) * 8 + h * 16) * 2;
                ldsm4t(vr, addr);
                mma_f16(oacc[0][2 * h],     aP[0], vr[0], vr[1]);
                mma_f16(oacc[0][2 * h + 1], aP[0], vr[2], vr[3]);
                mma_f16(oacc[1][2 * h],     aP[1], vr[0], vr[1]);
                mma_f16(oacc[1][2 * h + 1], aP[1], vr[2], vr[3]);
            }
        }
    }
    __syncthreads();   // all warps done with SMEM buffers

    // ---- combine key-halves via SMEM scratch ----
    float* sc = smf + wq * 1152;
    if (wk == 1) {
        int idx = 0;
#pragma unroll
        for (int m = 0; m < 2; m++)
#pragma unroll
            for (int n = 0; n < 4; n++)
#pragma unroll
                for (int r = 0; r < 4; r++)
                    sc[(idx++) * 32 + lane] = oacc[m][n][r];
#pragma unroll
        for (int m = 0; m < 2; m++)
#pragma unroll
            for (int r = 0; r < 2; r++)
                sc[1024 + (m * 2 + r) * 32 + lane] = lp[m][r];
    }
    __syncthreads();
    if (wk == 0) {
        int idx = 0;
#pragma unroll
        for (int m = 0; m < 2; m++)
#pragma unroll
            for (int n = 0; n < 4; n++)
#pragma unroll
                for (int r = 0; r < 4; r++)
                    oacc[m][n][r] += sc[(idx++) * 32 + lane];
#pragma unroll
        for (int m = 0; m < 2; m++)
#pragma unroll
            for (int r = 0; r < 2; r++)
                lp[m][r] += sc[1024 + (m * 2 + r) * 32 + lane];

#pragma unroll
        for (int m = 0; m < 2; m++)
#pragma unroll
            for (int r = 0; r < 2; r++) {
                float v = lp[m][r];
                v += __shfl_xor_sync(0xFFFFFFFFu, v, 1);
                v += __shfl_xor_sync(0xFFFFFFFFu, v, 2);
                lp[m][r] = 1.0f / v;
            }

        const int b  = bh >> 3;
        const int hh = bh & 7;
#pragma unroll
        for (int m = 0; m < 2; m++) {
            int q0 = qt * 128 + wq * 32 + m * 16 + gid;
#pragma unroll
            for (int n = 0; n < 4; n++) {
                int col = hh * 32 + n * 8 + 2 * tig;
                __half* p0 = Ch + (size_t)(b * N_ + q0) * D_ + col;
                __half* p1 = Ch + (size_t)(b * N_ + q0 + 8) * D_ + col;
                *(uint32_t*)p0 = f16x2(oacc[m][n][1] * lp[m][0],
                                       oacc[m][n][0] * lp[m][0]);
                *(uint32_t*)p1 = f16x2(oacc[m][n][3] * lp[m][1],
                                       oacc[m][n][2] * lp[m][1]);
            }
        }
    }
}

// ---------------------------------------------------------------------------
extern "C" void kernel_launch(void* const* d_in, const int* in_sizes, int n_in,
                              void* d_out, int out_size)
{
    const float* x  = (const float*)d_in[0];
    const float* Wq = (const float*)d_in[1];
    const float* bq = (const float*)d_in[2];
    const float* Wk = (const float*)d_in[3];
    const float* bk = (const float*)d_in[4];
    const float* Wv = (const float*)d_in[5];
    const float* bv = (const float*)d_in[6];
    const float* Wo = (const float*)d_in[7];
    const float* bo = (const float*)d_in[8];
    float* out = (float*)d_out;

    __half *qh, *kh, *vh, *xh, *wh, *ctxh;
    cudaGetSymbolAddress((void**)&qh,   g_qh_);
    cudaGetSymbolAddress((void**)&kh,   g_kh_);
    cudaGetSymbolAddress((void**)&vh,   g_vh_);
    cudaGetSymbolAddress((void**)&xh,   g_xh_);
    cudaGetSymbolAddress((void**)&wh,   g_wh_);
    cudaGetSymbolAddress((void**)&ctxh, g_ctxh_);

    cudaFuncSetAttribute(gemm_mma_kernel<1>,
                         cudaFuncAttributeMaxDynamicSharedMemorySize, GSM_BYTES);
    cudaFuncSetAttribute(gemm_mma_kernel<0>,
                         cudaFuncAttributeMaxDynamicSharedMemorySize, GSM_BYTES);
    cudaFuncSetAttribute(attn_mma_kernel,
                         cudaFuncAttributeMaxDynamicSharedMemorySize,
                         SMEM_ATTN_BYTES);

    cvt_kernel<<<296, 256>>>(x, Wq, Wk, Wv, Wo, xh, wh);

    dim3 qkv_grid(256 / 64, M_ / 64, 3);     // (4, 72, 3) = 864
    gemm_mma_kernel<1><<<qkv_grid, 256, GSM_BYTES>>>(
        xh, wh, bq, bk, bv, qh, kh, vh, nullptr);

    dim3 agrid(NTILE, BH_);                  // (18, 16)
    attn_mma_kernel<<<agrid, 256, SMEM_ATTN_BYTES>>>(qh, kh, vh, ctxh);

    dim3 o_grid(256 / 64, M_ / 64, 1);       // (4, 72, 1) = 288
    gemm_mma_kernel<0><<<o_grid, 256, GSM_BYTES>>>(
        ctxh, wh + 3 * D_ * D_, bo, bo, bo, nullptr, nullptr, nullptr, out);
}

// round 13
// speedup vs baseline: 1.0361x; 1.0034x over previous
#include <cuda_runtime.h>
#include <cuda_fp16.h>
#include <cstdint>

// ---------------------------------------------------------------------------
// TriangularAttention: B=2, S=48 -> N=2304, D=256, H=8, DH=32
// Round 13: 3-kernel plan. fp32->fp16 conversion folded into the GEMM load
//           phases (QKV reads fp32 x/W inline; O reads fp16 ctx via cp.async
//           + fp32 Wo inline). cvt kernel eliminated. Attention unchanged.
// ---------------------------------------------------------------------------

constexpr int B_  = 2;
constexpr int S_  = 48;
constexpr int D_  = 256;
constexpr int H_  = 8;
constexpr int DH_ = 32;
constexpr int N_  = S_ * S_;     // 2304
constexpr int M_  = B_ * N_;     // 4608
constexpr int BH_ = B_ * H_;     // 16

// fp16 storage (uint4 for 16B alignment)
__device__ uint4 g_qh_[BH_ * N_ * DH_ / 8];
__device__ uint4 g_kh_[BH_ * N_ * DH_ / 8];
__device__ uint4 g_vh_[BH_ * N_ * DH_ / 8];
__device__ uint4 g_ctxh_[M_ * D_ / 8];

// softmax: p = 2^(q·k·CS2 − C2); C2 cancels in the divide.
constexpr float CS2F = 0.17677669529663687f * 1.4426950408889634f;
constexpr float C2F  = 8.0f * 1.4426950408889634f;

// ---------------- helpers ---------------------------------------------------
__device__ __forceinline__ uint32_t f16x2(float hi, float lo) {  // {hi,lo}
    uint32_t r;
    asm("cvt.rn.f16x2.f32 %0, %1, %2;" : "=r"(r) : "f"(hi), "f"(lo));
    return r;
}
__device__ __forceinline__ uint32_t hadd2(uint32_t a, uint32_t b) {
    uint32_t d;
    asm("add.rn.f16x2 %0, %1, %2;" : "=r"(d) : "r"(a), "r"(b));
    return d;
}
__device__ __forceinline__ uint32_t h2ex2(uint32_t a) {
    uint32_t d;
    asm("ex2.approx.f16x2 %0, %1;" : "=r"(d) : "r"(a));
    return d;
}
__device__ __forceinline__ float2 h2f2(uint32_t h) {
    float lo, hi;
    asm("{ .reg .b16 l, m; mov.b32 {l, m}, %2;\n\t"
        "cvt.f32.f16 %0, l; cvt.f32.f16 %1, m; }"
        : "=f"(lo), "=f"(hi) : "r"(h));
    return make_float2(lo, hi);
}
__device__ __forceinline__ uint32_t smem_u32(const void* p) {
    uint32_t a;
    asm("{ .reg .u64 t; cvta.to.shared.u64 t, %1; cvt.u32.u64 %0, t; }"
        : "=r"(a) : "l"(p));
    return a;
}
__device__ __forceinline__ void mma_f16(float* d, const uint32_t* a,
                                        uint32_t b0, uint32_t b1) {
    asm volatile(
        "mma.sync.aligned.m16n8k16.row.col.f32.f16.f16.f32 "
        "{%0,%1,%2,%3}, {%4,%5,%6,%7}, {%8,%9}, {%0,%1,%2,%3};"
        : "+f"(d[0]), "+f"(d[1]), "+f"(d[2]), "+f"(d[3])
        : "r"(a[0]), "r"(a[1]), "r"(a[2]), "r"(a[3]), "r"(b0), "r"(b1));
}
__device__ __forceinline__ void ldsm4(uint32_t* r, uint32_t addr) {   // non-trans
    asm volatile(
        "ldmatrix.sync.aligned.m8n8.x4.shared.b16 {%0,%1,%2,%3}, [%4];"
        : "=r"(r[0]), "=r"(r[1]), "=r"(r[2]), "=r"(r[3]) : "r"(addr));
}
__device__ __forceinline__ void ldsm4t(uint32_t* r, uint32_t addr) {  // trans
    asm volatile(
        "ldmatrix.sync.aligned.m8n8.x4.trans.shared.b16 {%0,%1,%2,%3}, [%4];"
        : "=r"(r[0]), "=r"(r[1]), "=r"(r[2]), "=r"(r[3]) : "r"(addr));
}
__device__ __forceinline__ void cpa16(uint32_t dst, const void* src) {
    asm volatile("cp.async.cg.shared.global [%0], [%1], 16;"
                 :: "r"(dst), "l"(src));
}
__device__ __forceinline__ void cp_commit() {
    asm volatile("cp.async.commit_group;");
}
template <int NWAIT>
__device__ __forceinline__ void cp_wait() {
    asm volatile("cp.async.wait_group %0;" :: "n"(NWAIT));
}

// ---------------------------------------------------------------------------
// Common GEMM geometry: 64x64 CTA tile, full-K (256) residency.
// A [row][k] fp16, 528B stride; W [k][c] fp16, 144B stride.
// 8 warps (2 row x 4 col).
// ---------------------------------------------------------------------------
constexpr int AST = 528;
constexpr int WST = 144;
constexpr int GA_BYTES = 64 * AST;             // 33792
constexpr int GW_BYTES = 256 * WST;            // 36864
constexpr int GSM_BYTES = GA_BYTES + GW_BYTES; // 70656

// Compute + ldsm section shared by both GEMM kernels (after SMEM is ready).
__device__ __forceinline__ void gemm_core(
    uint32_t sb, uint32_t ws, int wr, int wc, int mm, int mr,
    float acc[2][2][4])
{
#pragma unroll
    for (int h = 0; h < 16; h++) {
        uint32_t a[2][4];
#pragma unroll
        for (int mt = 0; mt < 2; mt++) {
            uint32_t addr = sb
                + (uint32_t)(wr * 32 + mt * 16 + (mm & 1) * 8 + mr) * AST
                + (uint32_t)(h * 32 + (mm >> 1) * 16);
            ldsm4(a[mt], addr);
        }
        uint32_t w[4];
        {
            uint32_t addr = ws
                + (uint32_t)(h * 16 + (mm & 1) * 8 + mr) * WST
                + (uint32_t)(wc * 16 + (mm >> 1) * 8) * 2;
            ldsm4t(w, addr);
        }
        mma_f16(acc[0][0], a[0], w[0], w[1]);
        mma_f16(acc[0][1], a[0], w[2], w[3]);
        mma_f16(acc[1][0], a[1], w[0], w[1]);
        mma_f16(acc[1][1], a[1], w[2], w[3]);
    }
}

// ---------------------------------------------------------------------------
// QKV GEMM: reads fp32 x and fp32 W (inline cvt), writes fp16 head-major
// q/k/v (q pre-scaled by CS2). grid (4, 72, 3).
// ---------------------------------------------------------------------------
__global__ __launch_bounds__(256) void qkv_kernel(
    const float* __restrict__ x,
    const float* __restrict__ Wq, const float* __restrict__ Wk,
    const float* __restrict__ Wv,
    const float* __restrict__ bq, const float* __restrict__ bk,
    const float* __restrict__ bv,
    __half* __restrict__ qh, __half* __restrict__ kh,
    __half* __restrict__ vh)
{
    extern __shared__ __align__(16) char smc[];

    const int z = blockIdx.z;
    const float* W    = (z == 0) ? Wq : (z == 1) ? Wk : Wv;
    const float* bias = (z == 0) ? bq : (z == 1) ? bk : bv;
    __half* oh        = (z == 0) ? qh : (z == 1) ? kh : vh;
    const float sc    = (z == 0) ? CS2F : 1.0f;

    const int tid  = threadIdx.x;
    const int warp = tid >> 5;
    const int lane = tid & 31;
    const int gid  = lane >> 2;
    const int tig  = lane & 3;
    const int wr   = warp & 1;
    const int wc   = warp >> 1;
    const int c0   = blockIdx.x * 64;
    const int m0   = blockIdx.y * 64;
    const int mm   = lane >> 3;
    const int mr   = lane & 7;

    const uint32_t sb = smem_u32(smc);
    const uint32_t ws = sb + GA_BYTES;

    // ---- load + convert A slab: 64 rows x 256 fp32 ----
#pragma unroll 4
    for (int r = 0; r < 16; r++) {
        int idx = tid + r * 256;                // 0..4095
        int row = idx >> 6, c4 = idx & 63;
        float4 v = *(const float4*)&x[(size_t)(m0 + row) * 256 + c4 * 4];
        uint2 h;
        h.x = f16x2(v.y, v.x);
        h.y = f16x2(v.w, v.z);
        *(uint2*)(smc + row * AST + c4 * 8) = h;
    }
    // ---- load + convert W slab: 256 rows x 64 fp32 ----
#pragma unroll 4
    for (int r = 0; r < 16; r++) {
        int idx = tid + r * 256;                // 0..4095
        int row = idx >> 4, c4 = idx & 15;
        float4 v = *(const float4*)&W[(size_t)row * 256 + c0 + c4 * 4];
        uint2 h;
        h.x = f16x2(v.y, v.x);
        h.y = f16x2(v.w, v.z);
        *(uint2*)(smc + GA_BYTES + row * WST + c4 * 8) = h;
    }
    __syncthreads();

    float acc[2][2][4];
#pragma unroll
    for (int m = 0; m < 2; m++)
#pragma unroll
        for (int n = 0; n < 2; n++)
#pragma unroll
            for (int r = 0; r < 4; r++) acc[m][n][r] = 0.f;

    gemm_core(sb, ws, wr, wc, mm, mr, acc);

    // ---- epilogue: fp16 head-major, q scaled ----
#pragma unroll
    for (int n = 0; n < 2; n++) {
        int c = c0 + wc * 16 + n * 8 + 2 * tig;
        float bv0 = bias[c], bv1 = bias[c + 1];
#pragma unroll
        for (int m = 0; m < 2; m++) {
            int row = m0 + wr * 32 + m * 16 + gid;
            int hh = c >> 5;
            int dh = c & 31;
            int b  = row / N_;
            int nn = row - b * N_;
            __half* p = oh + (((size_t)(b * H_ + hh)) * N_ + nn) * DH_ + dh;
            *(uint32_t*)p = f16x2((acc[m][n][1] + bv1) * sc,
                                  (acc[m][n][0] + bv0) * sc);
            *(uint32_t*)(p + 8 * DH_) = f16x2((acc[m][n][3] + bv1) * sc,
                                              (acc[m][n][2] + bv0) * sc);
        }
    }
}

// ---------------------------------------------------------------------------
// O GEMM: ctx fp16 via cp.async, Wo fp32 inline cvt (overlaps cp.async),
// writes f32 row-major out. grid (4, 72).
// ---------------------------------------------------------------------------
__global__ __launch_bounds__(256) void ogemm_kernel(
    const __half* __restrict__ ctx, const float* __restrict__ Wo,
    const float* __restrict__ bo, float* __restrict__ outf)
{
    extern __shared__ __align__(16) char smc[];

    const int tid  = threadIdx.x;
    const int warp = tid >> 5;
    const int lane = tid & 31;
    const int gid  = lane >> 2;
    const int tig  = lane & 3;
    const int wr   = warp & 1;
    const int wc   = warp >> 1;
    const int c0   = blockIdx.x * 64;
    const int m0   = blockIdx.y * 64;
    const int mm   = lane >> 3;
    const int mr   = lane & 7;

    const uint32_t sb = smem_u32(smc);
    const uint32_t ws = sb + GA_BYTES;

    // ---- A slab (fp16 ctx): pure cp.async, issued first ----
    {
        const char* Ab = (const char*)(ctx + (size_t)m0 * 256);
#pragma unroll
        for (int r = 0; r < 8; r++) {           // 64 rows x 32 16B chunks
            int idx = tid + r * 256;
            int row = idx >> 5, c = idx & 31;
            cpa16(sb + row * AST + c * 16, Ab + (size_t)row * 512 + c * 16);
        }
    }
    cp_commit();

    // ---- W slab (fp32 Wo): inline cvt, overlaps the cp.async group ----
#pragma unroll 4
    for (int r = 0; r < 16; r++) {
        int idx = tid + r * 256;
        int row = idx >> 4, c4 = idx & 15;
        float4 v = *(const float4*)&Wo[(size_t)row * 256 + c0 + c4 * 4];
        uint2 h;
        h.x = f16x2(v.y, v.x);
        h.y = f16x2(v.w, v.z);
        *(uint2*)(smc + GA_BYTES + row * WST + c4 * 8) = h;
    }

    float acc[2][2][4];
#pragma unroll
    for (int m = 0; m < 2; m++)
#pragma unroll
        for (int n = 0; n < 2; n++)
#pragma unroll
            for (int r = 0; r < 4; r++) acc[m][n][r] = 0.f;

    cp_wait<0>();
    __syncthreads();

    gemm_core(sb, ws, wr, wc, mm, mr, acc);

    // ---- epilogue: f32 row-major + bias ----
#pragma unroll
    for (int n = 0; n < 2; n++) {
        int c = c0 + wc * 16 + n * 8 + 2 * tig;
        float bv0 = bo[c], bv1 = bo[c + 1];
#pragma unroll
        for (int m = 0; m < 2; m++) {
            int row = m0 + wr * 32 + m * 16 + gid;
            float* p = outf + (size_t)row * 256 + c;
            *(float2*)p = make_float2(acc[m][n][0] + bv0, acc[m][n][1] + bv1);
            *(float2*)(p + 8 * 256) =
                make_float2(acc[m][n][2] + bv0, acc[m][n][3] + bv1);
        }
    }
}

// ---------------------------------------------------------------------------
// fp16 flash attention (unchanged from rounds 9-12).
// ---------------------------------------------------------------------------
constexpr int NTILE = N_ / 128;   // 18
constexpr int KB0 = 0;
constexpr int KB1 = 128 * 80;     // 10240
constexpr int VB0 = 2 * 128 * 80;
constexpr int VB1 = VB0 + 128 * 80;
constexpr int SMEM_ATTN_BYTES = VB1 + 128 * 80;  // 40960

__global__ __launch_bounds__(256, 2) void attn_mma_kernel(
    const __half* __restrict__ Qh, const __half* __restrict__ Kh,
    const __half* __restrict__ Vh, __half* __restrict__ Ch)
{
    extern __shared__ __align__(16) float smf[];
    const int tid  = threadIdx.x;
    const int warp = tid >> 5;
    const int lane = tid & 31;
    const int gid  = lane >> 2;
    const int tig  = lane & 3;
    const int wq   = warp & 3;
    const int wk   = warp >> 2;
    const int bh   = blockIdx.y;
    const int qt   = blockIdx.x;
    const int mm   = lane >> 3;
    const int mr   = lane & 7;

    const uint32_t sb = smem_u32(smf);

    const __half* Qg = Qh + ((size_t)bh * N_ + qt * 128) * DH_;
    const __half* Kg = Kh + (size_t)bh * N_ * DH_;
    const __half* Vg = Vh + (size_t)bh * N_ * DH_;

    // ---- Q fp16 A-frags (pre-scaled at projection): direct uint loads ----
    uint32_t qa[2][2][4];
#pragma unroll
    for (int m = 0; m < 2; m++) {
        const __half* r0 = Qg + (size_t)(wq * 32 + m * 16 + gid) * DH_;
        const __half* r1 = r0 + 8 * DH_;
#pragma unroll
        for (int h = 0; h < 2; h++) {
            int k0 = h * 16 + 2 * tig;
            qa[m][h][0] = *(const uint32_t*)(r0 + k0);
            qa[m][h][1] = *(const uint32_t*)(r1 + k0);
            qa[m][h][2] = *(const uint32_t*)(r0 + k0 + 8);
            qa[m][h][3] = *(const uint32_t*)(r1 + k0 + 8);
        }
    }

    float oacc[2][4][4];
#pragma unroll
    for (int m = 0; m < 2; m++)
#pragma unroll
        for (int n = 0; n < 4; n++)
#pragma unroll
            for (int r = 0; r < 4; r++) oacc[m][n][r] = 0.f;
    float lp[2][2] = {{0.f, 0.f}, {0.f, 0.f}};

    // ---- cp.async tile loader: K,V 128 x 64B rows -> 80B stride SMEM ----
    auto load_tile = [&](int t, int buf) {
        uint32_t kd = sb + (buf ? KB1 : KB0);
        uint32_t vd = sb + (buf ? VB1 : VB0);
        const char* ks = (const char*)(Kg + (size_t)t * 128 * DH_);
        const char* vs = (const char*)(Vg + (size_t)t * 128 * DH_);
#pragma unroll
        for (int r = 0; r < 2; r++) {
            int idx = tid + r * 256;           // 0..511
            int row = idx >> 2, c = idx & 3;
            cpa16(kd + row * 80 + c * 16, ks + (size_t)row * 64 + c * 16);
            cpa16(vd + row * 80 + c * 16, vs + (size_t)row * 64 + c * 16);
        }
    };

    load_tile(0, 0);
    cp_commit();

    for (int t = 0; t < NTILE; t++) {
        const int buf = t & 1;
        cp_wait<0>();
        __syncthreads();
        if (t + 1 < NTILE) {
            load_tile(t + 1, buf ^ 1);
            cp_commit();
        }

        const uint32_t kbb = sb + (buf ? KB1 : KB0);
        const uint32_t vbb = sb + (buf ? VB1 : VB0);

#pragma unroll
        for (int g = 0; g < 4; g++) {
            const int kb = wk * 64 + g * 16;

            // ---- S = (scaled Q)·K^T − C2, fp16 MMA ----
            float s[2][2][4];
#pragma unroll
            for (int m = 0; m < 2; m++)
#pragma unroll
                for (int j = 0; j < 2; j++)
#pragma unroll
                    for (int r = 0; r < 4; r++) s[m][j][r] = -C2F;

#pragma unroll
            for (int h = 0; h < 2; h++) {
                uint32_t kr[4];
                uint32_t addr = kbb
                    + (uint32_t)(kb + (mm >> 1) * 8 + mr) * 80
                    + (uint32_t)((mm & 1) * 16 + h * 32);
                ldsm4(kr, addr);
                mma_f16(s[0][0], qa[0][h], kr[0], kr[1]);
                mma_f16(s[0][1], qa[0][h], kr[2], kr[3]);
                mma_f16(s[1][0], qa[1][h], kr[0], kr[1]);
                mma_f16(s[1][1], qa[1][h], kr[2], kr[3]);
            }

            // ---- p = 2^s in fp16 pairs; C-frag == A-frag identity ----
            uint32_t aP[2][4];
#pragma unroll
            for (int m = 0; m < 2; m++) {
                aP[m][0] = h2ex2(f16x2(s[m][0][1], s[m][0][0]));
                aP[m][1] = h2ex2(f16x2(s[m][0][3], s[m][0][2]));
                aP[m][2] = h2ex2(f16x2(s[m][1][1], s[m][1][0]));
                aP[m][3] = h2ex2(f16x2(s[m][1][3], s[m][1][2]));
                float2 f0 = h2f2(hadd2(aP[m][0], aP[m][2]));
                float2 f1 = h2f2(hadd2(aP[m][1], aP[m][3]));
                lp[m][0] += f0.x + f0.y;
                lp[m][1] += f1.x + f1.y;
            }

            // ---- O += P·V via trans ldmatrix + fp16 MMA ----
#pragma unroll
            for (int h = 0; h < 2; h++) {
                uint32_t vr[4];
                uint32_t addr = vbb
                    + (uint32_t)(kb + (mm & 1) * 8 + mr) * 80
                    + (uint32_t)((mm >> 1) * 8 + h * 16) * 2;
                ldsm4t(vr, addr);
                mma_f16(oacc[0][2 * h],     aP[0], vr[0], vr[1]);
                mma_f16(oacc[0][2 * h + 1], aP[0], vr[2], vr[3]);
                mma_f16(oacc[1][2 * h],     aP[1], vr[0], vr[1]);
                mma_f16(oacc[1][2 * h + 1], aP[1], vr[2], vr[3]);
            }
        }
    }
    __syncthreads();   // all warps done with SMEM buffers

    // ---- combine key-halves via SMEM scratch ----
    float* sc = smf + wq * 1152;
    if (wk == 1) {
        int idx = 0;
#pragma unroll
        for (int m = 0; m < 2; m++)
#pragma unroll
            for (int n = 0; n < 4; n++)
#pragma unroll
                for (int r = 0; r < 4; r++)
                    sc[(idx++) * 32 + lane] = oacc[m][n][r];
#pragma unroll
        for (int m = 0; m < 2; m++)
#pragma unroll
            for (int r = 0; r < 2; r++)
                sc[1024 + (m * 2 + r) * 32 + lane] = lp[m][r];
    }
    __syncthreads();
    if (wk == 0) {
        int idx = 0;
#pragma unroll
        for (int m = 0; m < 2; m++)
#pragma unroll
            for (int n = 0; n < 4; n++)
#pragma unroll
                for (int r = 0; r < 4; r++)
                    oacc[m][n][r] += sc[(idx++) * 32 + lane];
#pragma unroll
        for (int m = 0; m < 2; m++)
#pragma unroll
            for (int r = 0; r < 2; r++)
                lp[m][r] += sc[1024 + (m * 2 + r) * 32 + lane];

#pragma unroll
        for (int m = 0; m < 2; m++)
#pragma unroll
            for (int r = 0; r < 2; r++) {
                float v = lp[m][r];
                v += __shfl_xor_sync(0xFFFFFFFFu, v, 1);
                v += __shfl_xor_sync(0xFFFFFFFFu, v, 2);
                lp[m][r] = 1.0f / v;
            }

        const int b  = bh >> 3;
        const int hh = bh & 7;
#pragma unroll
        for (int m = 0; m < 2; m++) {
            int q0 = qt * 128 + wq * 32 + m * 16 + gid;
#pragma unroll
            for (int n = 0; n < 4; n++) {
                int col = hh * 32 + n * 8 + 2 * tig;
                __half* p0 = Ch + (size_t)(b * N_ + q0) * D_ + col;
                __half* p1 = Ch + (size_t)(b * N_ + q0 + 8) * D_ + col;
                *(uint32_t*)p0 = f16x2(oacc[m][n][1] * lp[m][0],
                                       oacc[m][n][0] * lp[m][0]);
                *(uint32_t*)p1 = f16x2(oacc[m][n][3] * lp[m][1],
                                       oacc[m][n][2] * lp[m][1]);
            }
        }
    }
}

// ---------------------------------------------------------------------------
extern "C" void kernel_launch(void* const* d_in, const int* in_sizes, int n_in,
                              void* d_out, int out_size)
{
    const float* x  = (const float*)d_in[0];
    const float* Wq = (const float*)d_in[1];
    const float* bq = (const float*)d_in[2];
    const float* Wk = (const float*)d_in[3];
    const float* bk = (const float*)d_in[4];
    const float* Wv = (const float*)d_in[5];
    const float* bv = (const float*)d_in[6];
    const float* Wo = (const float*)d_in[7];
    const float* bo = (const float*)d_in[8];
    float* out = (float*)d_out;

    __half *qh, *kh, *vh, *ctxh;
    cudaGetSymbolAddress((void**)&qh,   g_qh_);
    cudaGetSymbolAddress((void**)&kh,   g_kh_);
    cudaGetSymbolAddress((void**)&vh,   g_vh_);
    cudaGetSymbolAddress((void**)&ctxh, g_ctxh_);

    cudaFuncSetAttribute(qkv_kernel,
                         cudaFuncAttributeMaxDynamicSharedMemorySize, GSM_BYTES);
    cudaFuncSetAttribute(ogemm_kernel,
                         cudaFuncAttributeMaxDynamicSharedMemorySize, GSM_BYTES);
    cudaFuncSetAttribute(attn_mma_kernel,
                         cudaFuncAttributeMaxDynamicSharedMemorySize,
                         SMEM_ATTN_BYTES);

    dim3 qkv_grid(256 / 64, M_ / 64, 3);     // (4, 72, 3) = 864
    qkv_kernel<<<qkv_grid, 256, GSM_BYTES>>>(
        x, Wq, Wk, Wv, bq, bk, bv, qh, kh, vh);

    dim3 agrid(NTILE, BH_);                  // (18, 16)
    attn_mma_kernel<<<agrid, 256, SMEM_ATTN_BYTES>>>(qh, kh, vh, ctxh);

    dim3 o_grid(256 / 64, M_ / 64);          // (4, 72) = 288
    ogemm_kernel<<<o_grid, 256, GSM_BYTES>>>(ctxh, Wo, bo, out);
}